// round 13
// baseline (speedup 1.0000x reference)
#include <cuda_runtime.h>
#include <cuda_bf16.h>
#include <math.h>
#include <stdint.h>

#define N 8192
#define D 256
#define INVT (1.0f / 0.07f)
#define KC 64
#define NB 64                       // 8192/128 blocks per dim
#define NTILE (NB * (NB + 1) / 2)   // 2080 upper-triangular tiles
#define NPERS 296                   // persistent CTAs, 2 per SM (all resident)

__device__ __align__(16) __nv_bfloat16 g_fbf16[N * D];  // 4MB normalized bf16
__device__ float g_rowpart[NB * N];   // [cb][i]  2MB
__device__ float g_colpart[NB * N];   // [rb][j]  2MB
__device__ float g_posdot[N];
__device__ float g_blk[64];
__device__ unsigned int g_cnt;        // finalize ticket (self-resetting)
__device__ unsigned int g_bar;        // monotonic grid barrier (never reset)

// smem: A bufs 2x16KB @0, B bufs 2x16KB @32KB, reduce buffers after
#define SM_ROW  65536                 // float[128][2]  (1KB)
#define SM_COL  (65536 + 1024)        // float[128][4]  (2KB)
#define SMEM_TOTAL (65536 + 1024 + 2048)

// ---------------------------------------------------------------------------
__device__ __forceinline__ uint32_t smem_u32(const void* p) {
    uint32_t a;
    asm("{ .reg .u64 t; cvta.to.shared.u64 t, %1; cvt.u32.u64 %0, t; }" : "=r"(a) : "l"(p));
    return a;
}
#define SW128(o) ((o) ^ (((o) >> 3) & 0x70))

__device__ __forceinline__ void cpasync16(uint32_t s, const void* g) {
    asm volatile("cp.async.cg.shared.global [%0], [%1], 16;" :: "r"(s), "l"(g));
}
#define CP_COMMIT() asm volatile("cp.async.commit_group;" ::: "memory")
#define CP_WAIT(n)  asm volatile("cp.async.wait_group %0;" :: "n"(n) : "memory")

__device__ __forceinline__ void ldsm_x4(uint32_t& r0, uint32_t& r1, uint32_t& r2,
                                        uint32_t& r3, uint32_t a) {
    asm volatile("ldmatrix.sync.aligned.m8n8.x4.shared.b16 {%0,%1,%2,%3}, [%4];"
        : "=r"(r0), "=r"(r1), "=r"(r2), "=r"(r3) : "r"(a));
}
__device__ __forceinline__ void mma16816(float* c, const uint32_t* a,
                                         uint32_t b0, uint32_t b1) {
    asm volatile(
        "mma.sync.aligned.m16n8k16.row.col.f32.bf16.bf16.f32 "
        "{%0,%1,%2,%3},{%4,%5,%6,%7},{%8,%9},{%0,%1,%2,%3};"
        : "+f"(c[0]), "+f"(c[1]), "+f"(c[2]), "+f"(c[3])
        : "r"(a[0]), "r"(a[1]), "r"(a[2]), "r"(a[3]), "r"(b0), "r"(b1));
}

// Monotonic grid barrier: replay-safe (counter never resets), deadlock-free
// because all NPERS CTAs are co-resident.
__device__ __forceinline__ void grid_barrier() {
    __syncthreads();
    __shared__ unsigned int s_tgt;
    if (threadIdx.x == 0) {
        __threadfence();
        unsigned int t = atomicAdd(&g_bar, 1u);
        s_tgt = (t / NPERS + 1u) * NPERS;
    }
    __syncthreads();
    if (threadIdx.x == 0) {
        unsigned int tgt = s_tgt;
        while (true) {
            unsigned int v;
            asm volatile("ld.global.acquire.gpu.b32 %0, [%1];" : "=r"(v) : "l"(&g_bar));
            if (v >= tgt) break;
            __nanosleep(64);
        }
    }
    __syncthreads();
}

// ---------------------------------------------------------------------------
// ONE persistent kernel, 296 CTAs x 256 threads:
// normalize -> barrier -> sim GEMM tiles (R9 body) -> barrier -> finalize.
// ---------------------------------------------------------------------------
__global__ __launch_bounds__(256, 2) void ntxent_fused(const float* __restrict__ x,
                                                       float* __restrict__ out) {
    extern __shared__ __align__(1024) char smem[];
    const uint32_t sA0 = smem_u32(smem);
    const uint32_t sB0 = sA0 + 32768;
    float* sm_row = (float*)(smem + SM_ROW);   // [128][2]
    float* sm_col = (float*)(smem + SM_COL);   // [128][4]

    const int bid  = blockIdx.x;
    const int tid  = threadIdx.x;
    const int lane = tid & 31;
    const int warp = tid >> 5;

    // ===================== Phase A: normalize -> bf16 =====================
    // 256 chunks of 32 rows (8 warps x 4 rows); CTAs 0..255 take one each.
    for (int ch = bid; ch < 256; ch += NPERS) {
        const int row0 = ch * 32 + warp * 4;
        float4 v[4][2];
        #pragma unroll
        for (int r = 0; r < 4; r++) {
            const float* xr = x + (size_t)(row0 + r) * D + lane * 8;
            v[r][0] = *(const float4*)xr;
            v[r][1] = *(const float4*)(xr + 4);
        }
        float s[4];
        #pragma unroll
        for (int r = 0; r < 4; r++) {
            s[r] = v[r][0].x*v[r][0].x + v[r][0].y*v[r][0].y +
                   v[r][0].z*v[r][0].z + v[r][0].w*v[r][0].w +
                   v[r][1].x*v[r][1].x + v[r][1].y*v[r][1].y +
                   v[r][1].z*v[r][1].z + v[r][1].w*v[r][1].w;
        }
        #pragma unroll
        for (int o = 16; o > 0; o >>= 1) {
            #pragma unroll
            for (int r = 0; r < 4; r++) s[r] += __shfl_xor_sync(0xffffffffu, s[r], o);
        }
        #pragma unroll
        for (int r = 0; r < 4; r++) {
            const float rn = 1.0f / fmaxf(sqrtf(s[r]), 1e-8f);
            __nv_bfloat162 p[4];
            p[0] = __floats2bfloat162_rn(v[r][0].x*rn, v[r][0].y*rn);
            p[1] = __floats2bfloat162_rn(v[r][0].z*rn, v[r][0].w*rn);
            p[2] = __floats2bfloat162_rn(v[r][1].x*rn, v[r][1].y*rn);
            p[3] = __floats2bfloat162_rn(v[r][1].z*rn, v[r][1].w*rn);
            *(uint4*)(g_fbf16 + (size_t)(row0 + r) * D + lane * 8) = *(uint4*)p;
        }
    }

    grid_barrier();   // normalized features visible to all CTAs

    // ===================== Phase B: sim GEMM tiles (R9 body) ===============
    const int wm = warp >> 1;   // 0..3 (32-row slice)
    const int wn = warp & 1;    // 0..1 (64-col slice)
    const int sel = lane >> 3;
    const int sub = lane & 7;
    const int g   = lane >> 2;
    const int q   = lane & 3;

    for (int tile = bid; tile < NTILE; tile += NPERS) {
        int rb = 0, base = 0;
        while (base + (NB - rb) <= tile) { base += NB - rb; rb++; }
        const int cb = rb + (tile - base);
        const bool diag = (rb == cb);
        const int i0 = rb * 128;
        const int j0 = cb * 128;

        float c[2][8][4];
        #pragma unroll
        for (int mf = 0; mf < 2; mf++)
            #pragma unroll
            for (int nf = 0; nf < 8; nf++)
                #pragma unroll
                for (int e = 0; e < 4; e++) c[mf][nf][e] = 0.0f;
        float rs[2][2] = {{0.0f, 0.0f}, {0.0f, 0.0f}};

        auto load_chunk = [&](int kc, int bf) {
            const __nv_bfloat16* gA = g_fbf16 + (size_t)i0 * D + kc * KC;
            const __nv_bfloat16* gB = g_fbf16 + (size_t)j0 * D + kc * KC;
            const uint32_t dA = sA0 + bf * 16384;
            const uint32_t dB = sB0 + bf * 16384;
            #pragma unroll
            for (int v = 0; v < 4; v++) {
                int idx = tid + 256 * v;
                int r   = idx >> 3;
                int ci  = idx & 7;
                uint32_t so = SW128(r * 128 + ci * 16);
                cpasync16(dA + so, gA + (size_t)r * D + ci * 8);
                if (!diag) cpasync16(dB + so, gB + (size_t)r * D + ci * 8);
            }
        };
        auto load_a = [&](uint32_t bA, int ks, uint32_t a[2][4]) {
            #pragma unroll
            for (int mf = 0; mf < 2; mf++) {
                int row = wm * 32 + mf * 16 + (sel & 1) * 8 + sub;
                uint32_t off = (uint32_t)(row * 128 + ks * 32 + (sel >> 1) * 16);
                ldsm_x4(a[mf][0], a[mf][1], a[mf][2], a[mf][3], bA + SW128(off));
            }
        };
        auto load_b = [&](uint32_t bB, int ks, uint32_t b[4][4]) {
            #pragma unroll
            for (int p = 0; p < 4; p++) {
                int n = wn * 64 + p * 16 + (sel >> 1) * 8 + sub;
                uint32_t off = (uint32_t)(n * 128 + ks * 32 + (sel & 1) * 16);
                ldsm_x4(b[p][0], b[p][1], b[p][2], b[p][3], bB + SW128(off));
            }
        };

        load_chunk(0, 0);
        CP_COMMIT();

        const uint32_t sBbase = diag ? sA0 : sB0;

        for (int kc = 0; kc < 3; kc++) {
            CP_WAIT(0);
            __syncthreads();
            load_chunk(kc + 1, (kc + 1) & 1);
            CP_COMMIT();

            const uint32_t bA = sA0 + (kc & 1) * 16384;
            const uint32_t bB = sBbase + (kc & 1) * 16384;

            #pragma unroll
            for (int ks = 0; ks < 4; ks++) {
                uint32_t a[2][4], b[4][4];
                load_a(bA, ks, a);
                load_b(bB, ks, b);
                #pragma unroll
                for (int p = 0; p < 4; p++)
                    #pragma unroll
                    for (int mf = 0; mf < 2; mf++) {
                        mma16816(c[mf][2 * p],     a[mf], b[p][0], b[p][1]);
                        mma16816(c[mf][2 * p + 1], a[mf], b[p][2], b[p][3]);
                    }
            }
        }

        CP_WAIT(0);
        __syncthreads();
        {
            const uint32_t bA = sA0 + 16384;
            const uint32_t bB = sBbase + 16384;

            #pragma unroll
            for (int ks = 0; ks < 3; ks++) {
                uint32_t a[2][4], b[4][4];
                load_a(bA, ks, a);
                load_b(bB, ks, b);
                #pragma unroll
                for (int p = 0; p < 4; p++)
                    #pragma unroll
                    for (int mf = 0; mf < 2; mf++) {
                        mma16816(c[mf][2 * p],     a[mf], b[p][0], b[p][1]);
                        mma16816(c[mf][2 * p + 1], a[mf], b[p][2], b[p][3]);
                    }
            }

            // ks == 3: per nf, finish MMA then immediately run its epilogue.
            uint32_t a[2][4], b[4][4];
            load_a(bA, 3, a);
            load_b(bB, 3, b);
            #pragma unroll
            for (int p = 0; p < 4; p++) {
                #pragma unroll
                for (int half = 0; half < 2; half++) {
                    const int nf = 2 * p + half;
                    mma16816(c[0][nf], a[0], b[p][2 * half], b[p][2 * half + 1]);
                    mma16816(c[1][nf], a[1], b[p][2 * half], b[p][2 * half + 1]);

                    float s0 = 0.0f, s1 = 0.0f;
                    const int jb = j0 + wn * 64 + nf * 8 + 2 * q;
                    #pragma unroll
                    for (int mf = 0; mf < 2; mf++) {
                        #pragma unroll
                        for (int h = 0; h < 2; h++) {
                            const int i  = i0 + wm * 32 + mf * 16 + 8 * h + g;
                            const int pc = (i + N / 2) & (N - 1);
                            const float v0 = c[mf][nf][h * 2 + 0];
                            const float v1 = c[mf][nf][h * 2 + 1];
                            if (jb == pc)     { g_posdot[i] = v0; g_posdot[jb] = v0; }
                            if (jb + 1 == pc) { g_posdot[i] = v1; g_posdot[jb + 1] = v1; }
                            const float e0 = (jb != i)     ? __expf(v0 * INVT) : 0.0f;
                            const float e1 = (jb + 1 != i) ? __expf(v1 * INVT) : 0.0f;
                            rs[mf][h] += e0 + e1;
                            s0 += e0;
                            s1 += e1;
                        }
                    }
                    s0 += __shfl_xor_sync(0xffffffffu, s0, 4);
                    s0 += __shfl_xor_sync(0xffffffffu, s0, 8);
                    s0 += __shfl_xor_sync(0xffffffffu, s0, 16);
                    s1 += __shfl_xor_sync(0xffffffffu, s1, 4);
                    s1 += __shfl_xor_sync(0xffffffffu, s1, 8);
                    s1 += __shfl_xor_sync(0xffffffffu, s1, 16);
                    if (g == nf) {
                        const int jl = wn * 64 + nf * 8 + 2 * q;
                        sm_col[jl * 4 + wm]       = s0;
                        sm_col[(jl + 1) * 4 + wm] = s1;
                    }
                }
            }
        }

        #pragma unroll
        for (int mf = 0; mf < 2; mf++) {
            #pragma unroll
            for (int h = 0; h < 2; h++) {
                float v = rs[mf][h];
                v += __shfl_xor_sync(0xffffffffu, v, 1);
                v += __shfl_xor_sync(0xffffffffu, v, 2);
                if (q == 0) {
                    const int il = wm * 32 + mf * 16 + 8 * h + g;
                    sm_row[il * 2 + wn] = v;
                }
            }
        }
        __syncthreads();

        if (tid < 128) {
            g_rowpart[(size_t)cb * N + i0 + tid] = sm_row[tid * 2] + sm_row[tid * 2 + 1];
        } else if (!diag) {
            const int j = tid - 128;
            g_colpart[(size_t)rb * N + j0 + j] =
                sm_col[j * 4] + sm_col[j * 4 + 1] + sm_col[j * 4 + 2] + sm_col[j * 4 + 3];
        }
        __syncthreads();
    }

    grid_barrier();   // all partials visible

    // ===================== Phase C: finalize ===============================
    if (bid >= 64) return;
    {
        const int r = tid & 127;
        const int s = tid >> 7;
        const int i = bid * 128 + r;

        const float* basep = s ? g_colpart : g_rowpart;
        float acc = 0.0f;
        #pragma unroll 8
        for (int sp = 0; sp < NB; sp++) acc += basep[(size_t)sp * N + i];

        float* smf = (float*)smem;
        smf[tid] = acc;
        __syncthreads();

        float local = 0.0f;
        if (tid < 128) {
            const float tot = smf[tid] + smf[tid + 128];
            local = logf(tot) - g_posdot[i] * INVT;
        }
        #pragma unroll
        for (int o = 16; o > 0; o >>= 1) local += __shfl_xor_sync(0xffffffffu, local, o);

        __shared__ float ws[8];
        if ((tid & 31) == 0) ws[tid >> 5] = local;
        __syncthreads();
        if (tid == 0) {
            g_blk[bid] = ws[0] + ws[1] + ws[2] + ws[3];
            __threadfence();
            unsigned int tkt = atomicAdd(&g_cnt, 1u);
            if (tkt == 63u) {
                __threadfence();
                float tot = 0.0f;
                #pragma unroll 16
                for (int k = 0; k < 64; k++) tot += g_blk[k];
                out[0] = tot / (float)N;
                g_cnt = 0u;   // reset for next graph replay
            }
        }
    }
}

// ---------------------------------------------------------------------------
extern "C" void kernel_launch(void* const* d_in, const int* in_sizes, int n_in,
                              void* d_out, int out_size) {
    const float* features = (const float*)d_in[0];
    float* out = (float*)d_out;

    static bool attr_set = false;
    if (!attr_set) {
        cudaFuncSetAttribute(ntxent_fused, cudaFuncAttributeMaxDynamicSharedMemorySize,
                             SMEM_TOTAL);
        attr_set = true;
    }

    ntxent_fused<<<NPERS, 256, SMEM_TOTAL>>>(features, out);
}

// round 14
// speedup vs baseline: 1.0004x; 1.0004x over previous
#include <cuda_runtime.h>
#include <cuda_bf16.h>
#include <math.h>
#include <stdint.h>

#define N 8192
#define D 256
#define INVT (1.0f / 0.07f)
#define KC 64
#define NB 64                       // 8192/128 blocks per dim
#define NTILE (NB * (NB + 1) / 2)   // 2080 upper-triangular tiles

__device__ __align__(16) __nv_bfloat16 g_fbf16[N * D];  // 4MB normalized bf16
__device__ float g_sums[N];           // per-row exp-sum accumulators (atomic)
__device__ float g_posdot[N];
__device__ unsigned int g_done;       // tile-completion ticket

// smem layout: A bufs 2x16KB @0, B bufs 2x16KB @32KB, reduce buffers after
#define SM_ROW  65536                 // float[128][2]  (1KB)
#define SM_COL  (65536 + 1024)        // float[128][2]  (1KB)
#define SMEM_TOTAL (65536 + 2048)

// ---------------------------------------------------------------------------
__device__ __forceinline__ uint32_t smem_u32(const void* p) {
    uint32_t a;
    asm("{ .reg .u64 t; cvta.to.shared.u64 t, %1; cvt.u32.u64 %0, t; }" : "=r"(a) : "l"(p));
    return a;
}
#define SW128(o) ((o) ^ (((o) >> 3) & 0x70))

__device__ __forceinline__ void cpasync16(uint32_t s, const void* g) {
    asm volatile("cp.async.cg.shared.global [%0], [%1], 16;" :: "r"(s), "l"(g));
}
#define CP_COMMIT() asm volatile("cp.async.commit_group;" ::: "memory")
#define CP_WAIT(n)  asm volatile("cp.async.wait_group %0;" :: "n"(n) : "memory")

__device__ __forceinline__ void ldsm_x4(uint32_t& r0, uint32_t& r1, uint32_t& r2,
                                        uint32_t& r3, uint32_t a) {
    asm volatile("ldmatrix.sync.aligned.m8n8.x4.shared.b16 {%0,%1,%2,%3}, [%4];"
        : "=r"(r0), "=r"(r1), "=r"(r2), "=r"(r3) : "r"(a));
}
__device__ __forceinline__ void mma16816(float* c, const uint32_t* a,
                                         uint32_t b0, uint32_t b1) {
    asm volatile(
        "mma.sync.aligned.m16n8k16.row.col.f32.bf16.bf16.f32 "
        "{%0,%1,%2,%3},{%4,%5,%6,%7},{%8,%9},{%0,%1,%2,%3};"
        : "+f"(c[0]), "+f"(c[1]), "+f"(c[2]), "+f"(c[3])
        : "r"(a[0]), "r"(a[1]), "r"(a[2]), "r"(a[3]), "r"(b0), "r"(b1));
}

// ---------------------------------------------------------------------------
// Kernel 1: row L2-normalize -> bf16. 4 rows per warp (MLP=8).
// ---------------------------------------------------------------------------
__global__ void normalize_kernel(const float* __restrict__ x) {
    const int warp = threadIdx.x >> 5;
    const int lane = threadIdx.x & 31;
    const int row0 = blockIdx.x * 32 + warp * 4;

    float4 v[4][2];
    #pragma unroll
    for (int r = 0; r < 4; r++) {
        const float* xr = x + (size_t)(row0 + r) * D + lane * 8;
        v[r][0] = *(const float4*)xr;
        v[r][1] = *(const float4*)(xr + 4);
    }

    float s[4];
    #pragma unroll
    for (int r = 0; r < 4; r++) {
        s[r] = v[r][0].x*v[r][0].x + v[r][0].y*v[r][0].y +
               v[r][0].z*v[r][0].z + v[r][0].w*v[r][0].w +
               v[r][1].x*v[r][1].x + v[r][1].y*v[r][1].y +
               v[r][1].z*v[r][1].z + v[r][1].w*v[r][1].w;
    }
    #pragma unroll
    for (int o = 16; o > 0; o >>= 1) {
        #pragma unroll
        for (int r = 0; r < 4; r++) s[r] += __shfl_xor_sync(0xffffffffu, s[r], o);
    }

    #pragma unroll
    for (int r = 0; r < 4; r++) {
        const float rn = 1.0f / fmaxf(sqrtf(s[r]), 1e-8f);
        __nv_bfloat162 p[4];
        p[0] = __floats2bfloat162_rn(v[r][0].x*rn, v[r][0].y*rn);
        p[1] = __floats2bfloat162_rn(v[r][0].z*rn, v[r][0].w*rn);
        p[2] = __floats2bfloat162_rn(v[r][1].x*rn, v[r][1].y*rn);
        p[3] = __floats2bfloat162_rn(v[r][1].z*rn, v[r][1].w*rn);
        *(uint4*)(g_fbf16 + (size_t)(row0 + r) * D + lane * 8) = *(uint4*)p;
    }
}

// ---------------------------------------------------------------------------
// Kernel 2: HMMA fused sim GEMM (R11 body: 64x64 warp tiles, 128 threads),
// epilogue accumulates into g_sums via REDG; the last CTA to finish computes
// the final loss inline (no separate finalize kernel).
// ---------------------------------------------------------------------------
__global__ __launch_bounds__(128, 2) void simlse_mma(float* __restrict__ out) {
    extern __shared__ __align__(1024) char smem[];
    const uint32_t sA0 = smem_u32(smem);
    const uint32_t sB0 = sA0 + 32768;
    float* sm_row = (float*)(smem + SM_ROW);   // [128][2]
    float* sm_col = (float*)(smem + SM_COL);   // [128][2]

    // triangular tile map
    int t = blockIdx.x, rb = 0, base = 0;
    while (base + (NB - rb) <= t) { base += NB - rb; rb++; }
    const int cb = rb + (t - base);
    const bool diag = (rb == cb);

    const int tid  = threadIdx.x;
    const int lane = tid & 31;
    const int wm   = (tid >> 5) >> 1;   // 0..1 (64-row slice)
    const int wn   = (tid >> 5) & 1;    // 0..1 (64-col slice)
    const int i0   = rb * 128;
    const int j0   = cb * 128;

    const int sel = lane >> 3;
    const int sub = lane & 7;
    const int g   = lane >> 2;
    const int q   = lane & 3;

    float c[4][8][4];
    #pragma unroll
    for (int mf = 0; mf < 4; mf++)
        #pragma unroll
        for (int nf = 0; nf < 8; nf++)
            #pragma unroll
            for (int e = 0; e < 4; e++) c[mf][nf][e] = 0.0f;

    auto load_chunk = [&](int kc, int bf) {
        const __nv_bfloat16* gA = g_fbf16 + (size_t)i0 * D + kc * KC;
        const __nv_bfloat16* gB = g_fbf16 + (size_t)j0 * D + kc * KC;
        const uint32_t dA = sA0 + bf * 16384;
        const uint32_t dB = sB0 + bf * 16384;
        #pragma unroll
        for (int v = 0; v < 8; v++) {
            int idx = tid + 128 * v;   // 0..1023
            int r   = idx >> 3;        // 0..127
            int ci  = idx & 7;         // 16B unit
            uint32_t so = SW128(r * 128 + ci * 16);
            cpasync16(dA + so, gA + (size_t)r * D + ci * 8);
            if (!diag) cpasync16(dB + so, gB + (size_t)r * D + ci * 8);
        }
    };

    load_chunk(0, 0);
    CP_COMMIT();

    const uint32_t sBbase = diag ? sA0 : sB0;

    float rs[4][2];
    #pragma unroll
    for (int mf = 0; mf < 4; mf++) { rs[mf][0] = 0.0f; rs[mf][1] = 0.0f; }

    auto load_a = [&](uint32_t bA, int ks, uint32_t a[4][4]) {
        #pragma unroll
        for (int mf = 0; mf < 4; mf++) {
            int row = wm * 64 + mf * 16 + (sel & 1) * 8 + sub;
            uint32_t off = (uint32_t)(row * 128 + ks * 32 + (sel >> 1) * 16);
            ldsm_x4(a[mf][0], a[mf][1], a[mf][2], a[mf][3], bA + SW128(off));
        }
    };
    auto load_b = [&](uint32_t bB, int ks, uint32_t b[4][4]) {
        #pragma unroll
        for (int p = 0; p < 4; p++) {
            int n = wn * 64 + p * 16 + (sel >> 1) * 8 + sub;
            uint32_t off = (uint32_t)(n * 128 + ks * 32 + (sel & 1) * 16);
            ldsm_x4(b[p][0], b[p][1], b[p][2], b[p][3], bB + SW128(off));
        }
    };
    auto do_mma = [&](uint32_t a[4][4], uint32_t b[4][4]) {
        #pragma unroll
        for (int p = 0; p < 4; p++)
            #pragma unroll
            for (int mf = 0; mf < 4; mf++) {
                mma16816(c[mf][2 * p],     a[mf], b[p][0], b[p][1]);
                mma16816(c[mf][2 * p + 1], a[mf], b[p][2], b[p][3]);
            }
    };

    uint32_t afr[2][4][4], bfr[2][4][4];

    for (int kc = 0; kc < 4; kc++) {
        CP_WAIT(0);
        __syncthreads();
        if (kc < 3) { load_chunk(kc + 1, (kc + 1) & 1); CP_COMMIT(); }

        const uint32_t bA = sA0 + (kc & 1) * 16384;
        const uint32_t bB = sBbase + (kc & 1) * 16384;

        load_a(bA, 0, afr[0]);
        load_b(bB, 0, bfr[0]);

        if (kc < 3) {
            #pragma unroll
            for (int ks = 0; ks < 4; ks++) {
                const int cur = ks & 1;
                if (ks < 3) {
                    load_a(bA, ks + 1, afr[cur ^ 1]);
                    load_b(bB, ks + 1, bfr[cur ^ 1]);
                }
                do_mma(afr[cur], bfr[cur]);
            }
        } else {
            #pragma unroll
            for (int ks = 0; ks < 3; ks++) {
                const int cur = ks & 1;
                load_a(bA, ks + 1, afr[cur ^ 1]);
                load_b(bB, ks + 1, bfr[cur ^ 1]);
                do_mma(afr[cur], bfr[cur]);
            }
            // ks == 3 lives in afr[1]/bfr[1]: fuse the epilogue
            #pragma unroll
            for (int p = 0; p < 4; p++) {
                #pragma unroll
                for (int half = 0; half < 2; half++) {
                    const int nf = 2 * p + half;
                    #pragma unroll
                    for (int mf = 0; mf < 4; mf++)
                        mma16816(c[mf][nf], afr[1][mf],
                                 bfr[1][p][2 * half], bfr[1][p][2 * half + 1]);

                    float s0 = 0.0f, s1 = 0.0f;
                    const int jb = j0 + wn * 64 + nf * 8 + 2 * q;
                    #pragma unroll
                    for (int mf = 0; mf < 4; mf++) {
                        #pragma unroll
                        for (int h = 0; h < 2; h++) {
                            const int i  = i0 + wm * 64 + mf * 16 + 8 * h + g;
                            const int pc = (i + N / 2) & (N - 1);
                            const float v0 = c[mf][nf][h * 2 + 0];
                            const float v1 = c[mf][nf][h * 2 + 1];
                            if (jb == pc)     { g_posdot[i] = v0; g_posdot[jb] = v0; }
                            if (jb + 1 == pc) { g_posdot[i] = v1; g_posdot[jb + 1] = v1; }
                            const float e0 = (jb != i)     ? __expf(v0 * INVT) : 0.0f;
                            const float e1 = (jb + 1 != i) ? __expf(v1 * INVT) : 0.0f;
                            rs[mf][h] += e0 + e1;
                            s0 += e0;
                            s1 += e1;
                        }
                    }
                    s0 += __shfl_xor_sync(0xffffffffu, s0, 4);
                    s0 += __shfl_xor_sync(0xffffffffu, s0, 8);
                    s0 += __shfl_xor_sync(0xffffffffu, s0, 16);
                    s1 += __shfl_xor_sync(0xffffffffu, s1, 4);
                    s1 += __shfl_xor_sync(0xffffffffu, s1, 8);
                    s1 += __shfl_xor_sync(0xffffffffu, s1, 16);
                    if (g == nf) {
                        const int jl = wn * 64 + nf * 8 + 2 * q;
                        sm_col[jl * 2 + wm]       = s0;
                        sm_col[(jl + 1) * 2 + wm] = s1;
                    }
                }
            }
        }
    }

    // row partials: reduce over the 4 q-lanes, stash to smem
    #pragma unroll
    for (int mf = 0; mf < 4; mf++) {
        #pragma unroll
        for (int h = 0; h < 2; h++) {
            float v = rs[mf][h];
            v += __shfl_xor_sync(0xffffffffu, v, 1);
            v += __shfl_xor_sync(0xffffffffu, v, 2);
            if (q == 0) {
                const int il = wm * 64 + mf * 16 + 8 * h + g;
                sm_row[il * 2 + wn] = v;
            }
        }
    }
    __syncthreads();

    // accumulate into the single per-row sum array (coalesced REDG)
    atomicAdd(&g_sums[i0 + tid], sm_row[tid * 2] + sm_row[tid * 2 + 1]);
    if (!diag)
        atomicAdd(&g_sums[j0 + tid], sm_col[tid * 2] + sm_col[tid * 2 + 1]);

    // ---- last-done CTA computes the final loss inline ----
    __threadfence();
    __shared__ unsigned int s_tkt;
    if (tid == 0) s_tkt = atomicAdd(&g_done, 1u);
    __syncthreads();
    if (s_tkt == NTILE - 1) {
        __threadfence();
        float local = 0.0f;
        #pragma unroll 4
        for (int i = tid; i < N; i += 128) {
            const float s  = __ldcg(&g_sums[i]);
            const float pd = __ldcg(&g_posdot[i]);
            local += logf(s) - pd * INVT;
        }
        #pragma unroll
        for (int o = 16; o > 0; o >>= 1)
            local += __shfl_xor_sync(0xffffffffu, local, o);
        float* ws = (float*)smem;
        if (lane == 0) ws[tid >> 5] = local;
        __syncthreads();
        // reset accumulators for the next graph replay
        #pragma unroll 4
        for (int i = tid; i < N; i += 128) g_sums[i] = 0.0f;
        if (tid == 0) {
            out[0] = (ws[0] + ws[1] + ws[2] + ws[3]) / (float)N;
            g_done = 0u;
        }
    }
}

// ---------------------------------------------------------------------------
extern "C" void kernel_launch(void* const* d_in, const int* in_sizes, int n_in,
                              void* d_out, int out_size) {
    const float* features = (const float*)d_in[0];
    float* out = (float*)d_out;

    static bool attr_set = false;
    if (!attr_set) {
        cudaFuncSetAttribute(simlse_mma, cudaFuncAttributeMaxDynamicSharedMemorySize,
                             SMEM_TOTAL);
        attr_set = true;
    }

    normalize_kernel<<<N / 32, 256>>>(features);
    simlse_mma<<<NTILE, 128, SMEM_TOTAL>>>(out);
}

// round 15
// speedup vs baseline: 1.0272x; 1.0268x over previous
#include <cuda_runtime.h>
#include <cuda_bf16.h>
#include <math.h>
#include <stdint.h>

#define N 8192
#define D 256
#define INVT (1.0f / 0.07f)
#define KC 64
#define NB 64                       // 8192/128 blocks per dim
#define NTILE (NB * (NB + 1) / 2)   // 2080 upper-triangular tiles

__device__ __align__(16) __nv_bfloat16 g_fbf16[N * D];  // 4MB normalized bf16
__device__ float g_sums[N];           // per-row exp-sums (atomic accumulate)
__device__ float g_posdot[N];
__device__ float g_blk[8];
__device__ unsigned int g_cnt;        // finalize ticket (self-resetting)

// smem layout: A bufs 2x16KB @0, B bufs 2x16KB @32KB, reduce buffers after
#define SM_ROW  65536                 // float[128][2]  (1KB)
#define SM_COL  (65536 + 1024)        // float[128][2]  (1KB)
#define SMEM_TOTAL (65536 + 2048)

// ---------------------------------------------------------------------------
__device__ __forceinline__ uint32_t smem_u32(const void* p) {
    uint32_t a;
    asm("{ .reg .u64 t; cvta.to.shared.u64 t, %1; cvt.u32.u64 %0, t; }" : "=r"(a) : "l"(p));
    return a;
}
#define SW128(o) ((o) ^ (((o) >> 3) & 0x70))

__device__ __forceinline__ void cpasync16(uint32_t s, const void* g) {
    asm volatile("cp.async.cg.shared.global [%0], [%1], 16;" :: "r"(s), "l"(g));
}
#define CP_COMMIT() asm volatile("cp.async.commit_group;" ::: "memory")
#define CP_WAIT(n)  asm volatile("cp.async.wait_group %0;" :: "n"(n) : "memory")

__device__ __forceinline__ void ldsm_x4(uint32_t& r0, uint32_t& r1, uint32_t& r2,
                                        uint32_t& r3, uint32_t a) {
    asm volatile("ldmatrix.sync.aligned.m8n8.x4.shared.b16 {%0,%1,%2,%3}, [%4];"
        : "=r"(r0), "=r"(r1), "=r"(r2), "=r"(r3) : "r"(a));
}
__device__ __forceinline__ void mma16816(float* c, const uint32_t* a,
                                         uint32_t b0, uint32_t b1) {
    asm volatile(
        "mma.sync.aligned.m16n8k16.row.col.f32.bf16.bf16.f32 "
        "{%0,%1,%2,%3},{%4,%5,%6,%7},{%8,%9},{%0,%1,%2,%3};"
        : "+f"(c[0]), "+f"(c[1]), "+f"(c[2]), "+f"(c[3])
        : "r"(a[0]), "r"(a[1]), "r"(a[2]), "r"(a[3]), "r"(b0), "r"(b1));
}

// ---------------------------------------------------------------------------
// Kernel 1: row L2-normalize -> bf16. 4 rows per warp (MLP=8).
// ---------------------------------------------------------------------------
__global__ void normalize_kernel(const float* __restrict__ x) {
    const int warp = threadIdx.x >> 5;
    const int lane = threadIdx.x & 31;
    const int row0 = blockIdx.x * 32 + warp * 4;

    float4 v[4][2];
    #pragma unroll
    for (int r = 0; r < 4; r++) {
        const float* xr = x + (size_t)(row0 + r) * D + lane * 8;
        v[r][0] = *(const float4*)xr;
        v[r][1] = *(const float4*)(xr + 4);
    }

    float s[4];
    #pragma unroll
    for (int r = 0; r < 4; r++) {
        s[r] = v[r][0].x*v[r][0].x + v[r][0].y*v[r][0].y +
               v[r][0].z*v[r][0].z + v[r][0].w*v[r][0].w +
               v[r][1].x*v[r][1].x + v[r][1].y*v[r][1].y +
               v[r][1].z*v[r][1].z + v[r][1].w*v[r][1].w;
    }
    #pragma unroll
    for (int o = 16; o > 0; o >>= 1) {
        #pragma unroll
        for (int r = 0; r < 4; r++) s[r] += __shfl_xor_sync(0xffffffffu, s[r], o);
    }

    #pragma unroll
    for (int r = 0; r < 4; r++) {
        const float rn = 1.0f / fmaxf(sqrtf(s[r]), 1e-8f);
        __nv_bfloat162 p[4];
        p[0] = __floats2bfloat162_rn(v[r][0].x*rn, v[r][0].y*rn);
        p[1] = __floats2bfloat162_rn(v[r][0].z*rn, v[r][0].w*rn);
        p[2] = __floats2bfloat162_rn(v[r][1].x*rn, v[r][1].y*rn);
        p[3] = __floats2bfloat162_rn(v[r][1].z*rn, v[r][1].w*rn);
        *(uint4*)(g_fbf16 + (size_t)(row0 + r) * D + lane * 8) = *(uint4*)p;
    }
}

// ---------------------------------------------------------------------------
// Kernel 2: HMMA fused sim GEMM, 64x64 warp tiles (2x2 warps, 128 threads),
// NO fragment double-buffer (stay under the register cap), K-chunk double
// buffer, fused exp epilogue, atomic accumulation into g_sums.
// ---------------------------------------------------------------------------
__global__ __launch_bounds__(128, 2) void simlse_mma() {
    extern __shared__ __align__(1024) char smem[];
    const uint32_t sA0 = smem_u32(smem);
    const uint32_t sB0 = sA0 + 32768;
    float* sm_row = (float*)(smem + SM_ROW);   // [128][2]
    float* sm_col = (float*)(smem + SM_COL);   // [128][2]

    // triangular tile map
    int t = blockIdx.x, rb = 0, base = 0;
    while (base + (NB - rb) <= t) { base += NB - rb; rb++; }
    const int cb = rb + (t - base);
    const bool diag = (rb == cb);

    const int tid  = threadIdx.x;
    const int lane = tid & 31;
    const int wm   = (tid >> 5) >> 1;   // 0..1 (64-row slice)
    const int wn   = (tid >> 5) & 1;    // 0..1 (64-col slice)
    const int i0   = rb * 128;
    const int j0   = cb * 128;

    const int sel = lane >> 3;
    const int sub = lane & 7;
    const int g   = lane >> 2;
    const int q   = lane & 3;

    float c[4][8][4];
    #pragma unroll
    for (int mf = 0; mf < 4; mf++)
        #pragma unroll
        for (int nf = 0; nf < 8; nf++)
            #pragma unroll
            for (int e = 0; e < 4; e++) c[mf][nf][e] = 0.0f;

    auto load_chunk = [&](int kc, int bf) {
        const __nv_bfloat16* gA = g_fbf16 + (size_t)i0 * D + kc * KC;
        const __nv_bfloat16* gB = g_fbf16 + (size_t)j0 * D + kc * KC;
        const uint32_t dA = sA0 + bf * 16384;
        const uint32_t dB = sB0 + bf * 16384;
        #pragma unroll
        for (int v = 0; v < 8; v++) {
            int idx = tid + 128 * v;   // 0..1023
            int r   = idx >> 3;        // 0..127
            int ci  = idx & 7;         // 16B unit
            uint32_t so = SW128(r * 128 + ci * 16);
            cpasync16(dA + so, gA + (size_t)r * D + ci * 8);
            if (!diag) cpasync16(dB + so, gB + (size_t)r * D + ci * 8);
        }
    };

    load_chunk(0, 0);
    CP_COMMIT();

    const uint32_t sBbase = diag ? sA0 : sB0;

    float rs[4][2];
    #pragma unroll
    for (int mf = 0; mf < 4; mf++) { rs[mf][0] = 0.0f; rs[mf][1] = 0.0f; }

    auto load_a = [&](uint32_t bA, int ks, uint32_t a[4][4]) {
        #pragma unroll
        for (int mf = 0; mf < 4; mf++) {
            int row = wm * 64 + mf * 16 + (sel & 1) * 8 + sub;
            uint32_t off = (uint32_t)(row * 128 + ks * 32 + (sel >> 1) * 16);
            ldsm_x4(a[mf][0], a[mf][1], a[mf][2], a[mf][3], bA + SW128(off));
        }
    };
    auto load_b = [&](uint32_t bB, int ks, uint32_t b[4][4]) {
        #pragma unroll
        for (int p = 0; p < 4; p++) {
            int n = wn * 64 + p * 16 + (sel >> 1) * 8 + sub;
            uint32_t off = (uint32_t)(n * 128 + ks * 32 + (sel & 1) * 16);
            ldsm_x4(b[p][0], b[p][1], b[p][2], b[p][3], bB + SW128(off));
        }
    };
    auto do_mma = [&](uint32_t a[4][4], uint32_t b[4][4]) {
        #pragma unroll
        for (int p = 0; p < 4; p++)
            #pragma unroll
            for (int mf = 0; mf < 4; mf++) {
                mma16816(c[mf][2 * p],     a[mf], b[p][0], b[p][1]);
                mma16816(c[mf][2 * p + 1], a[mf], b[p][2], b[p][3]);
            }
    };

    for (int kc = 0; kc < 4; kc++) {
        CP_WAIT(0);
        __syncthreads();
        if (kc < 3) { load_chunk(kc + 1, (kc + 1) & 1); CP_COMMIT(); }

        const uint32_t bA = sA0 + (kc & 1) * 16384;
        const uint32_t bB = sBbase + (kc & 1) * 16384;

        if (kc < 3) {
            #pragma unroll
            for (int ks = 0; ks < 4; ks++) {
                uint32_t a[4][4], b[4][4];
                load_a(bA, ks, a);
                load_b(bB, ks, b);
                do_mma(a, b);
            }
        } else {
            #pragma unroll
            for (int ks = 0; ks < 3; ks++) {
                uint32_t a[4][4], b[4][4];
                load_a(bA, ks, a);
                load_b(bB, ks, b);
                do_mma(a, b);
            }
            // ks == 3: per nf, finish MMA then run that nf's epilogue
            uint32_t a[4][4], b[4][4];
            load_a(bA, 3, a);
            load_b(bB, 3, b);
            #pragma unroll
            for (int p = 0; p < 4; p++) {
                #pragma unroll
                for (int half = 0; half < 2; half++) {
                    const int nf = 2 * p + half;
                    #pragma unroll
                    for (int mf = 0; mf < 4; mf++)
                        mma16816(c[mf][nf], a[mf],
                                 b[p][2 * half], b[p][2 * half + 1]);

                    float s0 = 0.0f, s1 = 0.0f;
                    const int jb = j0 + wn * 64 + nf * 8 + 2 * q;
                    #pragma unroll
                    for (int mf = 0; mf < 4; mf++) {
                        #pragma unroll
                        for (int h = 0; h < 2; h++) {
                            const int i  = i0 + wm * 64 + mf * 16 + 8 * h + g;
                            const int pc = (i + N / 2) & (N - 1);
                            const float v0 = c[mf][nf][h * 2 + 0];
                            const float v1 = c[mf][nf][h * 2 + 1];
                            if (jb == pc)     { g_posdot[i] = v0; g_posdot[jb] = v0; }
                            if (jb + 1 == pc) { g_posdot[i] = v1; g_posdot[jb + 1] = v1; }
                            const float e0 = (jb != i)     ? __expf(v0 * INVT) : 0.0f;
                            const float e1 = (jb + 1 != i) ? __expf(v1 * INVT) : 0.0f;
                            rs[mf][h] += e0 + e1;
                            s0 += e0;
                            s1 += e1;
                        }
                    }
                    s0 += __shfl_xor_sync(0xffffffffu, s0, 4);
                    s0 += __shfl_xor_sync(0xffffffffu, s0, 8);
                    s0 += __shfl_xor_sync(0xffffffffu, s0, 16);
                    s1 += __shfl_xor_sync(0xffffffffu, s1, 4);
                    s1 += __shfl_xor_sync(0xffffffffu, s1, 8);
                    s1 += __shfl_xor_sync(0xffffffffu, s1, 16);
                    if (g == nf) {
                        const int jl = wn * 64 + nf * 8 + 2 * q;
                        sm_col[jl * 2 + wm]       = s0;
                        sm_col[(jl + 1) * 2 + wm] = s1;
                    }
                }
            }
        }
    }

    // row partials: reduce over the 4 q-lanes, stash to smem
    #pragma unroll
    for (int mf = 0; mf < 4; mf++) {
        #pragma unroll
        for (int h = 0; h < 2; h++) {
            float v = rs[mf][h];
            v += __shfl_xor_sync(0xffffffffu, v, 1);
            v += __shfl_xor_sync(0xffffffffu, v, 2);
            if (q == 0) {
                const int il = wm * 64 + mf * 16 + 8 * h + g;
                sm_row[il * 2 + wn] = v;
            }
        }
    }
    __syncthreads();

    // accumulate into the single per-row sum array (coalesced REDG)
    atomicAdd(&g_sums[i0 + tid], sm_row[tid * 2] + sm_row[tid * 2 + 1]);
    if (!diag)
        atomicAdd(&g_sums[j0 + tid], sm_col[tid * 2] + sm_col[tid * 2 + 1]);
}

// ---------------------------------------------------------------------------
// Kernel 3: tiny finalize. 8 blocks x 1024 threads, one row per thread;
// zeroes g_sums in place for the next graph replay.
// ---------------------------------------------------------------------------
__global__ void finalize_kernel(float* __restrict__ out) {
    const int tid = threadIdx.x;
    const int i   = blockIdx.x * 1024 + tid;

    const float s  = g_sums[i];
    const float pd = g_posdot[i];
    float local = logf(s) - pd * INVT;
    g_sums[i] = 0.0f;   // reset for next replay

    #pragma unroll
    for (int o = 16; o > 0; o >>= 1) local += __shfl_xor_sync(0xffffffffu, local, o);

    __shared__ float ws[32];
    if ((tid & 31) == 0) ws[tid >> 5] = local;
    __syncthreads();
    if (tid < 32) {
        float v = ws[tid];
        #pragma unroll
        for (int o = 16; o > 0; o >>= 1) v += __shfl_xor_sync(0xffffffffu, v, o);
        if (tid == 0) {
            g_blk[blockIdx.x] = v;
            __threadfence();
            unsigned int tkt = atomicAdd(&g_cnt, 1u);
            if (tkt == 7u) {
                __threadfence();
                float tot = 0.0f;
                #pragma unroll
                for (int k = 0; k < 8; k++) tot += g_blk[k];
                out[0] = tot / (float)N;
                g_cnt = 0u;   // reset for next replay
            }
        }
    }
}

// ---------------------------------------------------------------------------
extern "C" void kernel_launch(void* const* d_in, const int* in_sizes, int n_in,
                              void* d_out, int out_size) {
    const float* features = (const float*)d_in[0];
    float* out = (float*)d_out;

    static bool attr_set = false;
    if (!attr_set) {
        cudaFuncSetAttribute(simlse_mma, cudaFuncAttributeMaxDynamicSharedMemorySize,
                             SMEM_TOTAL);
        attr_set = true;
    }

    normalize_kernel<<<N / 32, 256>>>(features);
    simlse_mma<<<NTILE, 128, SMEM_TOTAL>>>();
    finalize_kernel<<<8, 1024>>>(out);
}

// round 16
// speedup vs baseline: 1.1153x; 1.0857x over previous
#include <cuda_runtime.h>
#include <cuda_bf16.h>
#include <math.h>
#include <stdint.h>

#define N 8192
#define D 256
#define INVT (1.0f / 0.07f)
#define KC 64
#define NB 64                       // 8192/128 blocks per dim
#define NTILE (NB * (NB + 1) / 2)   // 2080 upper-triangular tiles

__device__ __align__(16) __nv_bfloat16 g_fbf16[N * D];  // 4MB normalized bf16
__device__ float g_sums[N];           // per-row exp-sums (atomic accumulate)
__device__ float g_posdot[N];
__device__ float g_blk[8];
__device__ unsigned int g_cnt;        // finalize ticket (self-resetting)

// smem layout: A bufs 2x16KB @0, B bufs 2x16KB @32KB, reduce buffers after
#define SM_ROW  65536                 // float[128][2]  (1KB)
#define SM_COL  (65536 + 1024)        // float[128][2]  (1KB)
#define SMEM_TOTAL (65536 + 2048)

// ---------------------------------------------------------------------------
__device__ __forceinline__ uint32_t smem_u32(const void* p) {
    uint32_t a;
    asm("{ .reg .u64 t; cvta.to.shared.u64 t, %1; cvt.u32.u64 %0, t; }" : "=r"(a) : "l"(p));
    return a;
}
#define SW128(o) ((o) ^ (((o) >> 3) & 0x70))

__device__ __forceinline__ void cpasync16(uint32_t s, const void* g) {
    asm volatile("cp.async.cg.shared.global [%0], [%1], 16;" :: "r"(s), "l"(g));
}
#define CP_COMMIT() asm volatile("cp.async.commit_group;" ::: "memory")
#define CP_WAIT(n)  asm volatile("cp.async.wait_group %0;" :: "n"(n) : "memory")

__device__ __forceinline__ void ldsm_x4(uint32_t& r0, uint32_t& r1, uint32_t& r2,
                                        uint32_t& r3, uint32_t a) {
    asm volatile("ldmatrix.sync.aligned.m8n8.x4.shared.b16 {%0,%1,%2,%3}, [%4];"
        : "=r"(r0), "=r"(r1), "=r"(r2), "=r"(r3) : "r"(a));
}
__device__ __forceinline__ void mma16816(float* c, const uint32_t* a,
                                         uint32_t b0, uint32_t b1) {
    asm volatile(
        "mma.sync.aligned.m16n8k16.row.col.f32.bf16.bf16.f32 "
        "{%0,%1,%2,%3},{%4,%5,%6,%7},{%8,%9},{%0,%1,%2,%3};"
        : "+f"(c[0]), "+f"(c[1]), "+f"(c[2]), "+f"(c[3])
        : "r"(a[0]), "r"(a[1]), "r"(a[2]), "r"(a[3]), "r"(b0), "r"(b1));
}

// ---------------------------------------------------------------------------
// Kernel 1: row L2-normalize -> bf16. 4 rows per warp (MLP=8).
// ---------------------------------------------------------------------------
__global__ void normalize_kernel(const float* __restrict__ x) {
    const int warp = threadIdx.x >> 5;
    const int lane = threadIdx.x & 31;
    const int row0 = blockIdx.x * 32 + warp * 4;

    float4 v[4][2];
    #pragma unroll
    for (int r = 0; r < 4; r++) {
        const float* xr = x + (size_t)(row0 + r) * D + lane * 8;
        v[r][0] = *(const float4*)xr;
        v[r][1] = *(const float4*)(xr + 4);
    }

    float s[4];
    #pragma unroll
    for (int r = 0; r < 4; r++) {
        s[r] = v[r][0].x*v[r][0].x + v[r][0].y*v[r][0].y +
               v[r][0].z*v[r][0].z + v[r][0].w*v[r][0].w +
               v[r][1].x*v[r][1].x + v[r][1].y*v[r][1].y +
               v[r][1].z*v[r][1].z + v[r][1].w*v[r][1].w;
    }
    #pragma unroll
    for (int o = 16; o > 0; o >>= 1) {
        #pragma unroll
        for (int r = 0; r < 4; r++) s[r] += __shfl_xor_sync(0xffffffffu, s[r], o);
    }

    #pragma unroll
    for (int r = 0; r < 4; r++) {
        const float rn = 1.0f / fmaxf(sqrtf(s[r]), 1e-8f);
        __nv_bfloat162 p[4];
        p[0] = __floats2bfloat162_rn(v[r][0].x*rn, v[r][0].y*rn);
        p[1] = __floats2bfloat162_rn(v[r][0].z*rn, v[r][0].w*rn);
        p[2] = __floats2bfloat162_rn(v[r][1].x*rn, v[r][1].y*rn);
        p[3] = __floats2bfloat162_rn(v[r][1].z*rn, v[r][1].w*rn);
        *(uint4*)(g_fbf16 + (size_t)(row0 + r) * D + lane * 8) = *(uint4*)p;
    }
}

// ---------------------------------------------------------------------------
// Kernel 2: HMMA fused sim GEMM — R11 body verbatim (64x64 warp tiles,
// 128 threads, K-chunk + fragment double-buffer), epilogue accumulates
// into g_sums via coalesced atomicAdd. No finalize tail.
// ---------------------------------------------------------------------------
__global__ __launch_bounds__(128, 2) void simlse_mma() {
    extern __shared__ __align__(1024) char smem[];
    const uint32_t sA0 = smem_u32(smem);
    const uint32_t sB0 = sA0 + 32768;
    float* sm_row = (float*)(smem + SM_ROW);   // [128][2]
    float* sm_col = (float*)(smem + SM_COL);   // [128][2]

    // triangular tile map
    int t = blockIdx.x, rb = 0, base = 0;
    while (base + (NB - rb) <= t) { base += NB - rb; rb++; }
    const int cb = rb + (t - base);
    const bool diag = (rb == cb);

    const int tid  = threadIdx.x;
    const int lane = tid & 31;
    const int wm   = (tid >> 5) >> 1;   // 0..1 (64-row slice)
    const int wn   = (tid >> 5) & 1;    // 0..1 (64-col slice)
    const int i0   = rb * 128;
    const int j0   = cb * 128;

    const int sel = lane >> 3;
    const int sub = lane & 7;
    const int g   = lane >> 2;
    const int q   = lane & 3;

    float c[4][8][4];
    #pragma unroll
    for (int mf = 0; mf < 4; mf++)
        #pragma unroll
        for (int nf = 0; nf < 8; nf++)
            #pragma unroll
            for (int e = 0; e < 4; e++) c[mf][nf][e] = 0.0f;

    auto load_chunk = [&](int kc, int bf) {
        const __nv_bfloat16* gA = g_fbf16 + (size_t)i0 * D + kc * KC;
        const __nv_bfloat16* gB = g_fbf16 + (size_t)j0 * D + kc * KC;
        const uint32_t dA = sA0 + bf * 16384;
        const uint32_t dB = sB0 + bf * 16384;
        #pragma unroll
        for (int v = 0; v < 8; v++) {
            int idx = tid + 128 * v;   // 0..1023
            int r   = idx >> 3;        // 0..127
            int ci  = idx & 7;         // 16B unit
            uint32_t so = SW128(r * 128 + ci * 16);
            cpasync16(dA + so, gA + (size_t)r * D + ci * 8);
            if (!diag) cpasync16(dB + so, gB + (size_t)r * D + ci * 8);
        }
    };

    load_chunk(0, 0);
    CP_COMMIT();

    const uint32_t sBbase = diag ? sA0 : sB0;

    float rs[4][2];
    #pragma unroll
    for (int mf = 0; mf < 4; mf++) { rs[mf][0] = 0.0f; rs[mf][1] = 0.0f; }

    auto load_a = [&](uint32_t bA, int ks, uint32_t a[4][4]) {
        #pragma unroll
        for (int mf = 0; mf < 4; mf++) {
            int row = wm * 64 + mf * 16 + (sel & 1) * 8 + sub;
            uint32_t off = (uint32_t)(row * 128 + ks * 32 + (sel >> 1) * 16);
            ldsm_x4(a[mf][0], a[mf][1], a[mf][2], a[mf][3], bA + SW128(off));
        }
    };
    auto load_b = [&](uint32_t bB, int ks, uint32_t b[4][4]) {
        #pragma unroll
        for (int p = 0; p < 4; p++) {
            int n = wn * 64 + p * 16 + (sel >> 1) * 8 + sub;
            uint32_t off = (uint32_t)(n * 128 + ks * 32 + (sel & 1) * 16);
            ldsm_x4(b[p][0], b[p][1], b[p][2], b[p][3], bB + SW128(off));
        }
    };
    auto do_mma = [&](uint32_t a[4][4], uint32_t b[4][4]) {
        #pragma unroll
        for (int p = 0; p < 4; p++)
            #pragma unroll
            for (int mf = 0; mf < 4; mf++) {
                mma16816(c[mf][2 * p],     a[mf], b[p][0], b[p][1]);
                mma16816(c[mf][2 * p + 1], a[mf], b[p][2], b[p][3]);
            }
    };

    uint32_t afr[2][4][4], bfr[2][4][4];

    for (int kc = 0; kc < 4; kc++) {
        CP_WAIT(0);
        __syncthreads();
        if (kc < 3) { load_chunk(kc + 1, (kc + 1) & 1); CP_COMMIT(); }

        const uint32_t bA = sA0 + (kc & 1) * 16384;
        const uint32_t bB = sBbase + (kc & 1) * 16384;

        // prime fragment pipeline for this chunk
        load_a(bA, 0, afr[0]);
        load_b(bB, 0, bfr[0]);

        if (kc < 3) {
            #pragma unroll
            for (int ks = 0; ks < 4; ks++) {
                const int cur = ks & 1;
                if (ks < 3) {
                    load_a(bA, ks + 1, afr[cur ^ 1]);
                    load_b(bB, ks + 1, bfr[cur ^ 1]);
                }
                do_mma(afr[cur], bfr[cur]);
            }
        } else {
            // last chunk: ks 0-2 with prefetch, ks 3 fused with the epilogue
            #pragma unroll
            for (int ks = 0; ks < 3; ks++) {
                const int cur = ks & 1;
                load_a(bA, ks + 1, afr[cur ^ 1]);
                load_b(bB, ks + 1, bfr[cur ^ 1]);
                do_mma(afr[cur], bfr[cur]);
            }
            // ks == 3 lives in afr[1]/bfr[1]
            #pragma unroll
            for (int p = 0; p < 4; p++) {
                #pragma unroll
                for (int half = 0; half < 2; half++) {
                    const int nf = 2 * p + half;
                    #pragma unroll
                    for (int mf = 0; mf < 4; mf++)
                        mma16816(c[mf][nf], afr[1][mf],
                                 bfr[1][p][2 * half], bfr[1][p][2 * half + 1]);

                    // epilogue for this nf: 16 exps, row adds, col partials
                    float s0 = 0.0f, s1 = 0.0f;
                    const int jb = j0 + wn * 64 + nf * 8 + 2 * q;
                    #pragma unroll
                    for (int mf = 0; mf < 4; mf++) {
                        #pragma unroll
                        for (int h = 0; h < 2; h++) {
                            const int i  = i0 + wm * 64 + mf * 16 + 8 * h + g;
                            const int pc = (i + N / 2) & (N - 1);
                            const float v0 = c[mf][nf][h * 2 + 0];
                            const float v1 = c[mf][nf][h * 2 + 1];
                            if (jb == pc)     { g_posdot[i] = v0; g_posdot[jb] = v0; }
                            if (jb + 1 == pc) { g_posdot[i] = v1; g_posdot[jb + 1] = v1; }
                            const float e0 = (jb != i)     ? __expf(v0 * INVT) : 0.0f;
                            const float e1 = (jb + 1 != i) ? __expf(v1 * INVT) : 0.0f;
                            rs[mf][h] += e0 + e1;
                            s0 += e0;
                            s1 += e1;
                        }
                    }
                    s0 += __shfl_xor_sync(0xffffffffu, s0, 4);
                    s0 += __shfl_xor_sync(0xffffffffu, s0, 8);
                    s0 += __shfl_xor_sync(0xffffffffu, s0, 16);
                    s1 += __shfl_xor_sync(0xffffffffu, s1, 4);
                    s1 += __shfl_xor_sync(0xffffffffu, s1, 8);
                    s1 += __shfl_xor_sync(0xffffffffu, s1, 16);
                    if (g == nf) {
                        const int jl = wn * 64 + nf * 8 + 2 * q;
                        sm_col[jl * 2 + wm]       = s0;
                        sm_col[(jl + 1) * 2 + wm] = s1;
                    }
                }
            }
        }
    }

    // row partials: reduce over the 4 q-lanes, stash to smem
    #pragma unroll
    for (int mf = 0; mf < 4; mf++) {
        #pragma unroll
        for (int h = 0; h < 2; h++) {
            float v = rs[mf][h];
            v += __shfl_xor_sync(0xffffffffu, v, 1);
            v += __shfl_xor_sync(0xffffffffu, v, 2);
            if (q == 0) {
                const int il = wm * 64 + mf * 16 + 8 * h + g;
                sm_row[il * 2 + wn] = v;
            }
        }
    }
    __syncthreads();

    // accumulate into the single per-row sum array (coalesced REDG)
    atomicAdd(&g_sums[i0 + tid], sm_row[tid * 2] + sm_row[tid * 2 + 1]);
    if (!diag)
        atomicAdd(&g_sums[j0 + tid], sm_col[tid * 2] + sm_col[tid * 2 + 1]);
}

// ---------------------------------------------------------------------------
// Kernel 3: tiny finalize. 8 blocks x 1024 threads, one row per thread;
// zeroes g_sums in place for the next graph replay.
// ---------------------------------------------------------------------------
__global__ void finalize_kernel(float* __restrict__ out) {
    const int tid = threadIdx.x;
    const int i   = blockIdx.x * 1024 + tid;

    const float s  = g_sums[i];
    const float pd = g_posdot[i];
    float local = logf(s) - pd * INVT;
    g_sums[i] = 0.0f;   // reset for next replay

    #pragma unroll
    for (int o = 16; o > 0; o >>= 1) local += __shfl_xor_sync(0xffffffffu, local, o);

    __shared__ float ws[32];
    if ((tid & 31) == 0) ws[tid >> 5] = local;
    __syncthreads();
    if (tid < 32) {
        float v = ws[tid];
        #pragma unroll
        for (int o = 16; o > 0; o >>= 1) v += __shfl_xor_sync(0xffffffffu, v, o);
        if (tid == 0) {
            g_blk[blockIdx.x] = v;
            __threadfence();
            unsigned int tkt = atomicAdd(&g_cnt, 1u);
            if (tkt == 7u) {
                __threadfence();
                float tot = 0.0f;
                #pragma unroll
                for (int k = 0; k < 8; k++) tot += g_blk[k];
                out[0] = tot / (float)N;
                g_cnt = 0u;   // reset for next replay
            }
        }
    }
}

// ---------------------------------------------------------------------------
extern "C" void kernel_launch(void* const* d_in, const int* in_sizes, int n_in,
                              void* d_out, int out_size) {
    const float* features = (const float*)d_in[0];
    float* out = (float*)d_out;

    static bool attr_set = false;
    if (!attr_set) {
        cudaFuncSetAttribute(simlse_mma, cudaFuncAttributeMaxDynamicSharedMemorySize,
                             SMEM_TOTAL);
        attr_set = true;
    }

    normalize_kernel<<<N / 32, 256>>>(features);
    simlse_mma<<<NTILE, 128, SMEM_TOTAL>>>();
    finalize_kernel<<<8, 1024>>>(out);
}